// round 17
// baseline (speedup 1.0000x reference)
#include <cuda_runtime.h>
#include <cuda_bf16.h>

// CRF forward, scaled-probability domain, REGISTER-RESIDENT p with
// XOR-butterfly shuffle matvec. No shared-memory broadcast at all:
// the smem crossbar (128B/cyc/SM, broadcast delivers 32x) was the
// ~256 cyc/step roofline binding every previous smem variant.
//
//   feats      : (512, 1024, 32) f32
//   mask       : (512, 1024)     f32  (0/1 semantics)
//   transition : (32, 32)        f32
//   out        : (1024,)         f32
//
// alpha_t[j] = feat[t,b,j] + logsumexp_i(alpha_{t-1}[i] + T[j,i])
// p = exp(alpha - M), E' = 2^-6 exp(T):  q = E' p ; p' = q*(m*ef) + p*(1-m)
// 2^-6 prescale -> renorm period 16; correction exact: out += cnt*6ln2.
//
// Matvec: lane j holds p[j]; v_k = shfl_xor(p, k) = p[j^k] (immediate
// SHFL.BFLY, no per-lane index math); e[k] = E'[j][j^k] pre-rotated in
// registers. 31 SHFL + 32 FFMA into 4 accumulators. Chain never touches
// memory: SHFL(26) + FMA chain + tail ~= 75 cyc.
//
// Mapping: ONE batch per warp -> 1024 warps = 128 blocks x 256 threads =
// 2 warps per SMSP: the co-resident warp's instruction stream fills each
// chain's stall cycles.
//
// Loads: 1 feat LDG/step (8-deep ring). Mask: 1 LDG per 16 steps into a
// lane register, per-step value broadcast by immediate SHFL (no smem).
// em/om prepared one step ahead (keeps MUFU/LDS off the chain).

#define SEQ   512
#define BATCH 1024
#define TAGS  32
#define START_TAG 30
#define END_TAG   31
#define WPB   8
#define TPB   256
#define NBLOCKS 128
#define PERIOD 16
#define RING  8

#define CPRE        0.015625f                 // 2^-6 exact
#define LOG_CPREINV 4.1588830833596718f       // 6*ln2

__global__ __launch_bounds__(TPB, 1)
void crf_fwd_kernel(const float* __restrict__ feats,
                    const float* __restrict__ mask,
                    const float* __restrict__ trans,
                    float* __restrict__ out)
{
    const int j = threadIdx.x & 31;            // tag / lane
    const int w = threadIdx.x >> 5;            // warp in block
    const int b = blockIdx.x * WPB + w;        // this warp's batch

    // ---- E pre-rotated for XOR access: e[k] = E'[j][j^k] -----------------
    float e[TAGS];
#pragma unroll
    for (int k = 0; k < TAGS; ++k)
        e[k] = __expf(trans[j * TAGS + (j ^ k)]) * CPRE;
    const float eEnd = __expf(trans[END_TAG * TAGS + j]);

    // ---- init ------------------------------------------------------------
    float p    = (j == START_TAG) ? 1.0f : 0.0f;
    float M    = 0.0f;
    float cnt  = 0.0f;
    float pinv = 1.0f;                          // pending delayed scale

    // ---- feat ring (8 deep, 1 LDG/step) ----------------------------------
    const int fb = b * TAGS + j;
    float r[RING];
#pragma unroll
    for (int s = 0; s < RING; ++s)
        r[s] = feats[s * (BATCH * TAGS) + fb];

    // ---- mask chunks in lane registers (lane l holds step l of chunk) ----
    const int ml = j & 15;
    float mcur = mask[ml * BATCH + b];                   // chunk 0
    float mnxt = mask[(PERIOD + ml) * BATCH + b];        // chunk 1

    // ---- prepare step 0 (em/om one step ahead of use) --------------------
    float m0 = __shfl_sync(0xffffffffu, mcur, 0);
    float em = m0 * __expf(r[0]);
    float om = 1.0f - m0;
    float mc = m0;

    // ---- main recurrence: 32 chunks x 16 unrolled steps ------------------
    for (int c = 0; c < SEQ / PERIOD; ++c) {
        const int t0 = c * PERIOD;

#pragma unroll
        for (int u = 0; u < PERIOD; ++u) {
            const float emc = em, omc = om, mcc = mc;

            // prep em/om for step t+1 (ring slot loaded 7 steps ago)
            {
                const float mn = (u < PERIOD - 1)
                    ? __shfl_sync(0xffffffffu, mcur, u + 1)
                    : __shfl_sync(0xffffffffu, mnxt, 0);
                em = mn * __expf(r[(u + 1) & (RING - 1)]);
                om = 1.0f - mn;
                mc = mn;
            }

            // refill ring slot (u&7) with step t+8 (consumer 7 steps away)
            r[u & (RING - 1)] =
                feats[((t0 + u + RING) & (SEQ - 1)) * (BATCH * TAGS) + fb];

            // ---- matvec via XOR-butterfly shuffles -----------------------
            // q[j] = sum_k e[k] * p[j^k]; 31 immediate SHFL.BFLY + 32 FFMA
            float a0 = e[0] * p;
            float a1 = 0.0f, a2 = 0.0f, a3 = 0.0f;
#pragma unroll
            for (int k = 1; k < TAGS; ++k) {
                const float v = __shfl_xor_sync(0xffffffffu, p, k);
                if ((k & 3) == 0)      a0 = fmaf(e[k], v, a0);
                else if ((k & 3) == 1) a1 = fmaf(e[k], v, a1);
                else if ((k & 3) == 2) a2 = fmaf(e[k], v, a2);
                else                   a3 = fmaf(e[k], v, a3);
            }
            const float q = (a0 + a1) + (a2 + a3);

            // tail: p' = q*em + p*om
            p = fmaf(q, emc, p * omc);

            // applied-step counter (off-chain)
            cnt += mcc;

            // ---- delayed renorm, period 16 -------------------------------
            if (u == PERIOD - 1) {
                p *= pinv;                       // apply PREVIOUS scale
                float s = p;                     // snapshot max (off-chain)
#pragma unroll
                for (int off = 16; off > 0; off >>= 1)
                    s = fmaxf(s, __shfl_xor_sync(0xffffffffu, s, off));
                M += __logf(s);
                pinv = __frcp_rn(s);
            }
        }

        // rotate mask chunks: cur <- next, load chunk c+2 (wraps harmlessly)
        mcur = mnxt;
        mnxt = mask[((((c + 2) & 31) * PERIOD) + ml) * BATCH + b];
    }

    // ---- epilogue --------------------------------------------------------
    p *= pinv;                                   // final pending scale
    float ax = p * eEnd;
#pragma unroll
    for (int off = 16; off > 0; off >>= 1)
        ax += __shfl_xor_sync(0xffffffffu, ax, off);

    if (j == 0)
        out[b] = M + __logf(ax) + cnt * LOG_CPREINV;
}

extern "C" void kernel_launch(void* const* d_in, const int* in_sizes, int n_in,
                              void* d_out, int out_size)
{
    const float* feats = (const float*)d_in[0];
    const float* msk   = (const float*)d_in[1];
    const float* trans = (const float*)d_in[2];
    float*       o     = (float*)d_out;

    crf_fwd_kernel<<<NBLOCKS, TPB>>>(feats, msk, trans, o);
}